// round 1
// baseline (speedup 1.0000x reference)
#include <cuda_runtime.h>

#define NN 100000
#define EE 1600000
#define HH 64
#define GG 512
#define FULL 0xffffffffu

// ---------------- device scratch (no allocations allowed) ----------------
__device__ int   d_deg_in[NN];
__device__ int   d_deg_out[NN];
__device__ int   d_rowptr[NN + 1];
__device__ int   d_colptr[NN + 1];
__device__ int   d_rowcur[NN];
__device__ int   d_colcur[NN];
__device__ int   d_rowedges[EE];   // edge ids sorted by source (row)
__device__ int   d_colsrc[EE];     // source node ids sorted by target (col)
__device__ float d_colnorm[EE];    // dinv[src]*dinv[dst] per sorted-by-col slot
__device__ float d_dinv[NN];
__device__ float d_A[NN * 32];     // aggregated edge_attr per source node
__device__ float d_h[NN * HH];     // node features (agg output / gemm input)
__device__ float d_g[NN * HH];     // gemm output (agg input)

// ---------------- build degree histograms ----------------
__global__ void k_zero() {
    int i = blockIdx.x * blockDim.x + threadIdx.x;
    int s = gridDim.x * blockDim.x;
    for (; i < NN; i += s) { d_deg_in[i] = 0; d_deg_out[i] = 0; }
}

__global__ void k_count(const int* __restrict__ ei) {
    int i = blockIdx.x * blockDim.x + threadIdx.x;
    int s = gridDim.x * blockDim.x;
    for (; i < EE; i += s) {
        atomicAdd(&d_deg_out[ei[i]], 1);
        atomicAdd(&d_deg_in[ei[EE + i]], 1);
    }
}

// exclusive scan of both degree arrays; gridDim = 2
__global__ void k_scan() {
    __shared__ int sums[1024];
    const int* deg = (blockIdx.x == 0) ? d_deg_out : d_deg_in;
    int* ptr = (blockIdx.x == 0) ? d_rowptr : d_colptr;
    int* cur = (blockIdx.x == 0) ? d_rowcur : d_colcur;
    int t = threadIdx.x;
    const int CH = (NN + 1023) / 1024;
    int beg = t * CH;
    int end = min(beg + CH, NN);
    int s = 0;
    for (int i = beg; i < end; i++) s += deg[i];
    sums[t] = s;
    __syncthreads();
    for (int off = 1; off < 1024; off <<= 1) {
        int v = (t >= off) ? sums[t - off] : 0;
        __syncthreads();
        sums[t] += v;
        __syncthreads();
    }
    int excl = (t == 0) ? 0 : sums[t - 1];
    for (int i = beg; i < end; i++) {
        ptr[i] = excl; cur[i] = excl; excl += deg[i];
    }
    if (t == 1023) ptr[NN] = sums[1023];
}

__global__ void k_dinv() {
    int i = blockIdx.x * blockDim.x + threadIdx.x;
    if (i < NN) d_dinv[i] = rsqrtf((float)(d_deg_in[i] + 1));
}

__global__ void k_scatter(const int* __restrict__ ei) {
    int i = blockIdx.x * blockDim.x + threadIdx.x;
    int s = gridDim.x * blockDim.x;
    for (; i < EE; i += s) {
        int r = ei[i];
        int c = ei[EE + i];
        int p = atomicAdd(&d_rowcur[r], 1);
        d_rowedges[p] = i;
        int q = atomicAdd(&d_colcur[c], 1);
        d_colsrc[q] = r;
        d_colnorm[q] = d_dinv[r] * d_dinv[c];
    }
}

// ---------------- aggregate edge_attr at source nodes: A[n] = sum attr[e] ----
__global__ void k_aggattr(const float* __restrict__ ea) {
    int n = blockIdx.x * 8 + (threadIdx.x >> 5);
    int lane = threadIdx.x & 31;
    if (n >= NN) return;
    int beg = d_rowptr[n], end = d_rowptr[n + 1];
    float acc = 0.0f;
    for (int base = beg; base < end; base += 32) {
        int cnt = min(32, end - base);
        int ev = (base + lane < end) ? d_rowedges[base + lane] : 0;
        for (int t = 0; t < cnt; t++) {
            int e = __shfl_sync(FULL, ev, t);
            acc += ea[e * 32 + lane];
        }
    }
    d_A[n * 32 + lane] = acc;
}

// ---------------- h = x@Wn + A@We + bn + outdeg*be (fused embed) ------------
__global__ void k_gemm1(const float* __restrict__ x,
                        const float* __restrict__ Wn, const float* __restrict__ bn,
                        const float* __restrict__ We, const float* __restrict__ be) {
    __shared__ float2 sWn[128 * 32];
    __shared__ float2 sWe[32 * 32];
    __shared__ float  sbn[64], sbe[64];
    for (int idx = threadIdx.x; idx < 128 * 32; idx += 256) {
        int k = idx >> 5, j = idx & 31;
        sWn[idx] = make_float2(Wn[k * 64 + j], Wn[k * 64 + j + 32]);
    }
    for (int idx = threadIdx.x; idx < 32 * 32; idx += 256) {
        int k = idx >> 5, j = idx & 31;
        sWe[idx] = make_float2(We[k * 64 + j], We[k * 64 + j + 32]);
    }
    if (threadIdx.x < 64) { sbn[threadIdx.x] = bn[threadIdx.x]; sbe[threadIdx.x] = be[threadIdx.x]; }
    __syncthreads();

    int n = blockIdx.x * 8 + (threadIdx.x >> 5);
    int lane = threadIdx.x & 31;
    if (n >= NN) return;
    float xr0 = x[n * 128 + lane];
    float xr1 = x[n * 128 + 32 + lane];
    float xr2 = x[n * 128 + 64 + lane];
    float xr3 = x[n * 128 + 96 + lane];
    float ar  = d_A[n * 32 + lane];
    float ax = 0.0f, ay = 0.0f;
#pragma unroll
    for (int k = 0; k < 128; k++) {
        float src = (k < 32) ? xr0 : (k < 64) ? xr1 : (k < 96) ? xr2 : xr3;
        float xv = __shfl_sync(FULL, src, k & 31);
        float2 w = sWn[k * 32 + lane];
        ax = fmaf(xv, w.x, ax);
        ay = fmaf(xv, w.y, ay);
    }
#pragma unroll
    for (int k = 0; k < 32; k++) {
        float av = __shfl_sync(FULL, ar, k);
        float2 w = sWe[k * 32 + lane];
        ax = fmaf(av, w.x, ax);
        ay = fmaf(av, w.y, ay);
    }
    float dg = (float)d_deg_out[n];
    d_h[n * 64 + lane]      = ax + sbn[lane]      + dg * sbe[lane];
    d_h[n * 64 + 32 + lane] = ay + sbn[32 + lane] + dg * sbe[32 + lane];
}

// ---------------- g = h @ W (64x64) ----------------
__global__ void k_gemm64(const float* __restrict__ W) {
    __shared__ float2 sW[64 * 32];
    for (int idx = threadIdx.x; idx < 64 * 32; idx += 256) {
        int k = idx >> 5, j = idx & 31;
        sW[idx] = make_float2(W[k * 64 + j], W[k * 64 + j + 32]);
    }
    __syncthreads();
    int n = blockIdx.x * 8 + (threadIdx.x >> 5);
    int lane = threadIdx.x & 31;
    if (n >= NN) return;
    float hr0 = d_h[n * 64 + lane];
    float hr1 = d_h[n * 64 + 32 + lane];
    float ax = 0.0f, ay = 0.0f;
#pragma unroll
    for (int k = 0; k < 64; k++) {
        float src = (k < 32) ? hr0 : hr1;
        float hv = __shfl_sync(FULL, src, k & 31);
        float2 w = sW[k * 32 + lane];
        ax = fmaf(hv, w.x, ax);
        ay = fmaf(hv, w.y, ay);
    }
    d_g[n * 64 + lane]      = ax;
    d_g[n * 64 + 32 + lane] = ay;
}

// ---------------- h[c] = sum_{e:col=c} norm*g[src] + dinv[c]^2*g[c] + b ------
__global__ void k_agg(const float* __restrict__ bias, int do_relu) {
    int n = blockIdx.x * 8 + (threadIdx.x >> 5);
    int lane = threadIdx.x & 31;
    if (n >= NN) return;
    int beg = d_colptr[n], end = d_colptr[n + 1];
    float sl = d_dinv[n];
    sl *= sl;
    float a0 = sl * d_g[n * 64 + lane];
    float a1 = sl * d_g[n * 64 + 32 + lane];
    for (int base = beg; base < end; base += 32) {
        int cnt = min(32, end - base);
        int   sv = (base + lane < end) ? d_colsrc[base + lane]  : 0;
        float nv = (base + lane < end) ? d_colnorm[base + lane] : 0.0f;
        for (int t = 0; t < cnt; t++) {
            int s   = __shfl_sync(FULL, sv, t);
            float w = __shfl_sync(FULL, nv, t);
            a0 = fmaf(w, d_g[s * 64 + lane],      a0);
            a1 = fmaf(w, d_g[s * 64 + 32 + lane], a1);
        }
    }
    float o0 = a0 + bias[lane];
    float o1 = a1 + bias[32 + lane];
    if (do_relu) { o0 = fmaxf(o0, 0.0f); o1 = fmaxf(o1, 0.0f); }
    d_h[n * 64 + lane]      = o0;
    d_h[n * 64 + 32 + lane] = o1;
}

// ---------------- mean pool (sorted batch) + classifier ----------------
__device__ __forceinline__ int lbound(const int* a, int n, int v) {
    int lo = 0, hi = n;
    while (lo < hi) {
        int mid = (lo + hi) >> 1;
        if (a[mid] < v) lo = mid + 1; else hi = mid;
    }
    return lo;
}

__global__ void k_classifier(const int* __restrict__ batch,
                             const float* __restrict__ Wc1, const float* __restrict__ bc1,
                             const float* __restrict__ Wc2, const float* __restrict__ bc2,
                             float* __restrict__ out) {
    int g = blockIdx.x * 8 + (threadIdx.x >> 5);
    int lane = threadIdx.x & 31;
    if (g >= GG) return;
    int lo = 0, hi = 0;
    if (lane == 0) {
        lo = lbound(batch, NN, g);
        hi = lbound(batch, NN, g + 1);
    }
    lo = __shfl_sync(FULL, lo, 0);
    hi = __shfl_sync(FULL, hi, 0);
    float s0 = 0.0f, s1 = 0.0f;
    for (int n = lo; n < hi; n++) {
        s0 += d_h[n * 64 + lane];
        s1 += d_h[n * 64 + 32 + lane];
    }
    float cnt = (float)(hi - lo);
    float inv = (cnt > 0.0f) ? 1.0f / cnt : 0.0f;
    float m0 = s0 * inv, m1 = s1 * inv;
    float hid = bc1[lane];
#pragma unroll
    for (int k = 0; k < 64; k++) {
        float mk = (k < 32) ? __shfl_sync(FULL, m0, k) : __shfl_sync(FULL, m1, k - 32);
        hid = fmaf(mk, Wc1[k * 32 + lane], hid);
    }
    hid = fmaxf(hid, 0.0f);
    float v = hid * Wc2[lane];
#pragma unroll
    for (int off = 16; off; off >>= 1) v += __shfl_xor_sync(FULL, v, off);
    if (lane == 0) out[g] = v + bc2[0];
}

// ---------------- launch ----------------
extern "C" void kernel_launch(void* const* d_in, const int* in_sizes, int n_in,
                              void* d_out, int out_size) {
    const float* x    = (const float*)d_in[0];
    const int*   ei   = (const int*)  d_in[1];
    const float* ea   = (const float*)d_in[2];
    const int*   batch= (const int*)  d_in[3];
    const float* Wn   = (const float*)d_in[4];
    const float* bn   = (const float*)d_in[5];
    const float* We   = (const float*)d_in[6];
    const float* be   = (const float*)d_in[7];
    const float* Wg1  = (const float*)d_in[8];
    const float* bg1  = (const float*)d_in[9];
    const float* Wg2  = (const float*)d_in[10];
    const float* bg2  = (const float*)d_in[11];
    const float* Wg3  = (const float*)d_in[12];
    const float* bg3  = (const float*)d_in[13];
    const float* Wc1  = (const float*)d_in[14];
    const float* bc1  = (const float*)d_in[15];
    const float* Wc2  = (const float*)d_in[16];
    const float* bc2  = (const float*)d_in[17];
    float* out = (float*)d_out;

    const int WB = (NN + 7) / 8;  // warp-per-node blocks (8 warps/block)

    k_zero<<<256, 256>>>();
    k_count<<<2048, 256>>>(ei);
    k_scan<<<2, 1024>>>();
    k_dinv<<<(NN + 255) / 256, 256>>>();
    k_scatter<<<2048, 256>>>(ei);
    k_aggattr<<<WB, 256>>>(ea);
    k_gemm1<<<WB, 256>>>(x, Wn, bn, We, be);

    k_gemm64<<<WB, 256>>>(Wg1);
    k_agg<<<WB, 256>>>(bg1, 1);
    k_gemm64<<<WB, 256>>>(Wg2);
    k_agg<<<WB, 256>>>(bg2, 1);
    k_gemm64<<<WB, 256>>>(Wg3);
    k_agg<<<WB, 256>>>(bg3, 0);

    k_classifier<<<64, 256>>>(batch, Wc1, bc1, Wc2, bc2, out);
}